// round 5
// baseline (speedup 1.0000x reference)
#include <cuda_runtime.h>
#include <cuda_bf16.h>
#include <math.h>
#include <stdint.h>

#define NNODES 50000
#define NEDGES 800000

// ---------------------------------------------------------------------------
// Scratch (__device__ globals; no cudaMalloc allowed)
// ---------------------------------------------------------------------------
__device__ float g_xl[NNODES * 128];
__device__ float g_xr[NNODES * 128];
__device__ float g_h[NNODES * 128];      // layer input (post-ELU)
__device__ float g_acc[NNODES * 128];    // residual accumulator (A@res + b)
__device__ int   g_src[NEDGES];
__device__ int   g_dst[NEDGES];
__device__ int   g_srcSorted[NEDGES];    // src ids grouped by dst (CSR)
__device__ int   g_deg[NNODES];
__device__ int   g_cnt[NNODES];
__device__ int   g_rowptr[NNODES + 1];
__device__ int   g_is64;

// ---------------------------------------------------------------------------
// Helpers
// ---------------------------------------------------------------------------
__device__ __forceinline__ uint32_t smem_u32(const void* p) {
    uint32_t a;
    asm("{ .reg .u64 t; cvta.to.shared.u64 t, %1; cvt.u32.u64 %0, t; }"
        : "=r"(a) : "l"(p));
    return a;
}

__device__ __forceinline__ void ldsm_x4(uint32_t& r0, uint32_t& r1,
                                        uint32_t& r2, uint32_t& r3, uint32_t addr) {
    asm volatile("ldmatrix.sync.aligned.m8n8.x4.shared.b16 {%0,%1,%2,%3}, [%4];"
                 : "=r"(r0), "=r"(r1), "=r"(r2), "=r"(r3) : "r"(addr));
}

__device__ __forceinline__ void mma_bf16(float* c, const uint32_t* a,
                                         uint32_t b0, uint32_t b1) {
    asm volatile(
        "mma.sync.aligned.m16n8k16.row.col.f32.bf16.bf16.f32 "
        "{%0,%1,%2,%3}, {%4,%5,%6,%7}, {%8,%9}, {%0,%1,%2,%3};"
        : "+f"(c[0]), "+f"(c[1]), "+f"(c[2]), "+f"(c[3])
        : "r"(a[0]), "r"(a[1]), "r"(a[2]), "r"(a[3]), "r"(b0), "r"(b1));
}

// ---------------------------------------------------------------------------
// Edge index decode (int64 vs int32 robust) + CSR build
// ---------------------------------------------------------------------------
__global__ void detect_kernel(const void* ei) {
    if (threadIdx.x == 0 && blockIdx.x == 0) {
        const long long* p = (const long long*)ei;
        int ok = 1;
        for (int i = 0; i < 64; i++) {
            long long v = p[i];
            if (v < 0 || v >= NNODES) { ok = 0; break; }
        }
        g_is64 = ok;
    }
}

__global__ void decode_hist_kernel(const void* ei, int E) {
    int i = blockIdx.x * blockDim.x + threadIdx.x;
    if (i >= E) return;
    int s, d;
    if (g_is64) {
        const long long* p = (const long long*)ei;
        s = (int)p[i];
        d = (int)p[(size_t)E + i];
    } else {
        const int* p = (const int*)ei;
        s = p[i];
        d = p[E + i];
    }
    g_src[i] = s;
    g_dst[i] = d;
    atomicAdd(&g_deg[d], 1);
}

__global__ void scan_kernel(int n) {
    __shared__ int ssum[1024];
    const int tid = threadIdx.x;
    const int chunk = (n + 1023) >> 10;
    const int b = tid * chunk;
    const int e = min(b + chunk, n);
    int s = 0;
    for (int i = b; i < e; i++) s += g_deg[i];
    ssum[tid] = s;
    __syncthreads();
    for (int off = 1; off < 1024; off <<= 1) {
        int v = (tid >= off) ? ssum[tid - off] : 0;
        __syncthreads();
        ssum[tid] += v;
        __syncthreads();
    }
    int run = (tid > 0) ? ssum[tid - 1] : 0;
    for (int i = b; i < e; i++) { g_rowptr[i] = run; run += g_deg[i]; }
    if (tid == 0) g_rowptr[n] = ssum[1023];
}

__global__ void scatter_kernel(int E) {
    int i = blockIdx.x * blockDim.x + threadIdx.x;
    if (i >= E) return;
    int d = g_dst[i];
    int pos = g_rowptr[d] + atomicAdd(&g_cnt[d], 1);
    g_srcSorted[pos] = g_src[i];
}

// ---------------------------------------------------------------------------
// Tensor-core (mma.sync bf16, split precision) fused multi-GEMM.
//   For each matrix i: C_i[nrows, NC] = A[nrows,128] @ B_i[128, NC] + bias_i
//   A = A_hi + A_lo (bf16), B likewise; acc = hi*hi + hi*lo + lo*hi in fp32.
// One CTA per 128-row tile, 256 threads (8 warps x 16 rows).
// SMEM padded row stride 136 bf16 -> ldmatrix conflict-free.
// ---------------------------------------------------------------------------
#define LDSR 136   // padded row stride in bf16 elements

template <int NC, int NMATS>
__global__ __launch_bounds__(256)
void gemm_mma_kernel(const float* __restrict__ A,
                     const float* __restrict__ Bm0, const float* __restrict__ bias0, float* __restrict__ C0,
                     const float* __restrict__ Bm1, const float* __restrict__ bias1, float* __restrict__ C1,
                     const float* __restrict__ Bm2, const float* __restrict__ bias2, float* __restrict__ C2,
                     int nrows)
{
    extern __shared__ __nv_bfloat16 sm[];
    __nv_bfloat16* sAhi = sm;                       // 128 x LDSR
    __nv_bfloat16* sAlo = sm + 128 * LDSR;
    __nv_bfloat16* sBhi = sm + 2 * 128 * LDSR;      // NC x LDSR (Bt: row n, K contiguous)
    __nv_bfloat16* sBlo = sm + 2 * 128 * LDSR + NC * LDSR;

    const int tid  = threadIdx.x;
    const int wid  = tid >> 5;
    const int lane = tid & 31;
    const int row0 = blockIdx.x * 128;

    // --- load A tile, split hi/lo ---
    for (int it = 0; it < 16; it++) {
        int idx4 = it * 256 + tid;         // 128 rows x 32 float4
        int r = idx4 >> 5, c4 = idx4 & 31;
        int k = c4 * 4;
        int gr = row0 + r;
        float4 v = make_float4(0.f, 0.f, 0.f, 0.f);
        if (gr < nrows) v = *(const float4*)(A + (size_t)gr * 128 + k);
        __nv_bfloat16 h[4], l[4];
        h[0] = __float2bfloat16_rn(v.x); l[0] = __float2bfloat16_rn(v.x - __bfloat162float(h[0]));
        h[1] = __float2bfloat16_rn(v.y); l[1] = __float2bfloat16_rn(v.y - __bfloat162float(h[1]));
        h[2] = __float2bfloat16_rn(v.z); l[2] = __float2bfloat16_rn(v.z - __bfloat162float(h[2]));
        h[3] = __float2bfloat16_rn(v.w); l[3] = __float2bfloat16_rn(v.w - __bfloat162float(h[3]));
        *(uint2*)(sAhi + r * LDSR + k) = *(const uint2*)h;
        *(uint2*)(sAlo + r * LDSR + k) = *(const uint2*)l;
    }

    const float* Bms[3]   = {Bm0, Bm1, Bm2};
    const float* biasm[3] = {bias0, bias1, bias2};
    float*       Cm[3]    = {C0, C1, C2};

    const uint32_t uAhi = smem_u32(sAhi);
    const uint32_t uAlo = smem_u32(sAlo);
    const uint32_t uBhi = smem_u32(sBhi);
    const uint32_t uBlo = smem_u32(sBlo);

    // ldmatrix lane addressing (byte offsets into padded tiles)
    const int a_row = wid * 16 + (lane & 15);
    const int a_koff = (lane >> 4) * 8;
    const int b_row_in16 = (lane & 7) + ((lane & 16) ? 8 : 0);
    const int b_koff = ((lane >> 3) & 1) * 8;

    #pragma unroll 1
    for (int mat = 0; mat < NMATS; mat++) {
        __syncthreads();   // prev acc consumed / A tile ready
        // --- load B transposed + split: gmem B[k][n] -> sB[n][k] ---
        const float* B = Bms[mat];
        for (int idx = tid; idx < 128 * NC; idx += 256) {
            int k = idx / NC;
            int n = idx - k * NC;
            float v = B[idx];
            __nv_bfloat16 h = __float2bfloat16_rn(v);
            __nv_bfloat16 l = __float2bfloat16_rn(v - __bfloat162float(h));
            sBhi[n * LDSR + k] = h;
            sBlo[n * LDSR + k] = l;
        }
        __syncthreads();

        float acc[NC / 8][4];
        #pragma unroll
        for (int nf = 0; nf < NC / 8; nf++)
            #pragma unroll
            for (int j = 0; j < 4; j++) acc[nf][j] = 0.0f;

        #pragma unroll
        for (int ks = 0; ks < 8; ks++) {
            const uint32_t a_off = (uint32_t)(a_row * LDSR + ks * 16 + a_koff) * 2u;
            uint32_t ahi[4], alo[4];
            ldsm_x4(ahi[0], ahi[1], ahi[2], ahi[3], uAhi + a_off);
            ldsm_x4(alo[0], alo[1], alo[2], alo[3], uAlo + a_off);

            #pragma unroll
            for (int nf2 = 0; nf2 < NC / 16; nf2++) {
                const uint32_t b_off =
                    (uint32_t)((nf2 * 16 + b_row_in16) * LDSR + ks * 16 + b_koff) * 2u;
                uint32_t bh[4], bl[4];
                ldsm_x4(bh[0], bh[1], bh[2], bh[3], uBhi + b_off);
                ldsm_x4(bl[0], bl[1], bl[2], bl[3], uBlo + b_off);
                // even n-frag (cols nf2*16 .. +7): regs {0,1}; odd: {2,3}
                mma_bf16(acc[nf2 * 2 + 0], ahi, bh[0], bh[1]);
                mma_bf16(acc[nf2 * 2 + 0], ahi, bl[0], bl[1]);
                mma_bf16(acc[nf2 * 2 + 0], alo, bh[0], bh[1]);
                mma_bf16(acc[nf2 * 2 + 1], ahi, bh[2], bh[3]);
                mma_bf16(acc[nf2 * 2 + 1], ahi, bl[2], bl[3]);
                mma_bf16(acc[nf2 * 2 + 1], alo, bh[2], bh[3]);
            }
        }

        // --- epilogue: bias + store ---
        const float* bias = biasm[mat];
        float* C = Cm[mat];
        const int r_lo = row0 + wid * 16 + (lane >> 2);
        const int r_hi = r_lo + 8;
        #pragma unroll
        for (int nf = 0; nf < NC / 8; nf++) {
            const int col = nf * 8 + (lane & 3) * 2;
            const float b0 = bias[col], b1 = bias[col + 1];
            if (r_lo < nrows) {
                float2 o = make_float2(acc[nf][0] + b0, acc[nf][1] + b1);
                *(float2*)(C + (size_t)r_lo * NC + col) = o;
            }
            if (r_hi < nrows) {
                float2 o = make_float2(acc[nf][2] + b0, acc[nf][3] + b1);
                *(float2*)(C + (size_t)r_hi * NC + col) = o;
            }
        }
    }
}

// ---------------------------------------------------------------------------
// Warp-per-node GATv2 aggregation with online softmax.
// ---------------------------------------------------------------------------
template <int H, int C, bool RESELU>
__global__ void gat_aggregate_kernel(const float* __restrict__ xl,
                                     const float* __restrict__ xr,
                                     const float* __restrict__ att,
                                     const float* __restrict__ extra,
                                     float* __restrict__ out, int N)
{
    constexpr int HC = H * C;
    constexpr int R  = HC / 32;
    constexpr int L  = 32 / H;
    const int n = (blockIdx.x * blockDim.x + threadIdx.x) >> 5;
    if (n >= N) return;
    const int lane = threadIdx.x & 31;
    const int fo = lane * R;

    float xrv[R], attv[R], acc[R];
    #pragma unroll
    for (int j = 0; j < R; j++) {
        xrv[j]  = xr[(size_t)n * HC + fo + j];
        attv[j] = att[fo + j];
        acc[j]  = 0.0f;
    }
    float m   = __int_as_float(0xff800000);
    float den = 0.0f;

    const int beg = g_rowptr[n], end = g_rowptr[n + 1];
    for (int i = beg; i < end; i++) {
        const int s = g_srcSorted[i];
        float a[R];
        if (R == 4) {
            float4 t = *(const float4*)(xl + (size_t)s * HC + fo);
            a[0] = t.x; a[1] = t.y; a[2] = t.z; a[3] = t.w;
        } else {
            float2 t = *(const float2*)(xl + (size_t)s * HC + fo);
            a[0] = t.x; a[1] = t.y;
        }
        float lg = 0.0f;
        #pragma unroll
        for (int j = 0; j < R; j++) {
            float v = a[j] + xrv[j];
            v = v > 0.0f ? v : 0.2f * v;
            lg += v * attv[j];
        }
        #pragma unroll
        for (int off = L >> 1; off; off >>= 1)
            lg += __shfl_xor_sync(0xffffffffu, lg, off);

        float mn = fmaxf(m, lg);
        float sc = __expf(m - mn);
        float p  = __expf(lg - mn);
        den = den * sc + p;
        #pragma unroll
        for (int j = 0; j < R; j++) acc[j] = acc[j] * sc + p * a[j];
        m = mn;
    }

    const float inv = 1.0f / (den + 1e-16f);
    #pragma unroll
    for (int j = 0; j < R; j++) {
        float v = acc[j] * inv;
        if (RESELU) {
            v += extra[(size_t)n * HC + fo + j];
            v = v > 0.0f ? v : (__expf(v) - 1.0f);
        } else {
            v += extra[fo + j];
        }
        out[(size_t)n * HC + fo + j] = v;
    }
}

// ---------------------------------------------------------------------------
// Launch
// ---------------------------------------------------------------------------
extern "C" void kernel_launch(void* const* d_in, const int* in_sizes, int n_in,
                              void* d_out, int out_size) {
    const float* x    = (const float*)d_in[0];
    const void*  ei   = d_in[1];
    const float* Wl0  = (const float*)d_in[2];
    const float* bl0  = (const float*)d_in[3];
    const float* Wr0  = (const float*)d_in[4];
    const float* br0  = (const float*)d_in[5];
    const float* att0 = (const float*)d_in[6];
    const float* b0   = (const float*)d_in[7];
    const float* res0 = (const float*)d_in[8];
    const float* Wl1  = (const float*)d_in[9];
    const float* bl1  = (const float*)d_in[10];
    const float* Wr1  = (const float*)d_in[11];
    const float* br1  = (const float*)d_in[12];
    const float* att1 = (const float*)d_in[13];
    const float* b1   = (const float*)d_in[14];
    const float* res1 = (const float*)d_in[15];
    const float* Wl2  = (const float*)d_in[16];
    const float* bl2  = (const float*)d_in[17];
    const float* Wr2  = (const float*)d_in[18];
    const float* br2  = (const float*)d_in[19];
    const float* att2 = (const float*)d_in[20];
    const float* b2   = (const float*)d_in[21];
    float* out = (float*)d_out;

    const int N = in_sizes[0] / 128;
    const int E = in_sizes[1] / 2;

    float *p_xl, *p_xr, *p_h, *p_acc;
    int *p_deg, *p_cnt;
    cudaGetSymbolAddress((void**)&p_xl,  g_xl);
    cudaGetSymbolAddress((void**)&p_xr,  g_xr);
    cudaGetSymbolAddress((void**)&p_h,   g_h);
    cudaGetSymbolAddress((void**)&p_acc, g_acc);
    cudaGetSymbolAddress((void**)&p_deg, g_deg);
    cudaGetSymbolAddress((void**)&p_cnt, g_cnt);

    // dynamic smem: A(2 tiles) + B(2 tiles), padded stride
    const int sm3 = (2 * 128 * LDSR + 2 * 128 * LDSR) * 2;  // NC=128 -> 139264 B
    const int sm2 = (2 * 128 * LDSR + 2 * 64 * LDSR) * 2;   // NC=64  -> 104448 B
    static bool attr_done = false;
    if (!attr_done) {
        cudaFuncSetAttribute(gemm_mma_kernel<128, 3>,
                             cudaFuncAttributeMaxDynamicSharedMemorySize, sm3);
        cudaFuncSetAttribute(gemm_mma_kernel<64, 2>,
                             cudaFuncAttributeMaxDynamicSharedMemorySize, sm2);
        attr_done = true;
    }

    const int TB = 256;
    const int gemm_blocks = (N + 127) / 128;
    const int node_blocks = (N + 7) / 8;

    // ---- CSR build ----
    detect_kernel<<<1, 32>>>(ei);
    cudaMemsetAsync(p_deg, 0, (size_t)N * sizeof(int), 0);
    cudaMemsetAsync(p_cnt, 0, (size_t)N * sizeof(int), 0);
    decode_hist_kernel<<<(E + TB - 1) / TB, TB>>>(ei, E);
    scan_kernel<<<1, 1024>>>(N);
    scatter_kernel<<<(E + TB - 1) / TB, TB>>>(E);

    // ---- layer 0 ----
    gemm_mma_kernel<128, 3><<<gemm_blocks, TB, sm3>>>(
        x, Wl0, bl0, p_xl, Wr0, br0, p_xr, res0, b0, p_acc, N);
    gat_aggregate_kernel<4, 32, true><<<node_blocks, TB>>>(p_xl, p_xr, att0,
                                                           p_acc, p_h, N);
    // ---- layer 1 ----
    gemm_mma_kernel<128, 3><<<gemm_blocks, TB, sm3>>>(
        p_h, Wl1, bl1, p_xl, Wr1, br1, p_xr, res1, b1, p_acc, N);
    gat_aggregate_kernel<4, 32, true><<<node_blocks, TB>>>(p_xl, p_xr, att1,
                                                           p_acc, p_h, N);
    // ---- layer 2 ----
    gemm_mma_kernel<64, 2><<<gemm_blocks, TB, sm2>>>(
        p_h, Wl2, bl2, p_xl, Wr2, br2, p_xr,
        (const float*)0, (const float*)0, (float*)0, N);
    gat_aggregate_kernel<1, 64, false><<<node_blocks, TB>>>(p_xl, p_xr, att2,
                                                            b2, out, N);
}

// round 6
// speedup vs baseline: 1.1422x; 1.1422x over previous
#include <cuda_runtime.h>
#include <math.h>
#include <stdint.h>

#define NNODES 50000
#define NEDGES 800000

// ---------------------------------------------------------------------------
// Scratch (__device__ globals; no cudaMalloc allowed)
// ---------------------------------------------------------------------------
__device__ float g_xl[NNODES * 128];
__device__ float g_xr[NNODES * 128];
__device__ float g_h[NNODES * 128];      // layer input (post-ELU)
__device__ float g_acc[NNODES * 128];    // residual accumulator (A@res + b)
__device__ int   g_src[NEDGES];
__device__ int   g_dst[NEDGES];
__device__ int   g_srcSorted[NEDGES];    // src ids grouped by dst (CSR)
__device__ int   g_deg[NNODES];
__device__ int   g_cnt[NNODES];
__device__ int   g_rowptr[NNODES + 1];
__device__ int   g_is64;

// ---------------------------------------------------------------------------
// Packed f32x2 helpers (sm_100+ PTX)
// ---------------------------------------------------------------------------
__device__ __forceinline__ uint64_t pack2(float x) {
    uint64_t r;
    asm("mov.b64 %0, {%1, %1};" : "=l"(r) : "f"(x));
    return r;
}
__device__ __forceinline__ void fma2(uint64_t& d, uint64_t a, uint64_t b) {
    asm("fma.rn.f32x2 %0, %1, %2, %0;" : "+l"(d) : "l"(a), "l"(b));
}
__device__ __forceinline__ float2 unpack2(uint64_t v) {
    float2 r;
    asm("mov.b64 {%0, %1}, %2;" : "=f"(r.x), "=f"(r.y) : "l"(v));
    return r;
}

// ---------------------------------------------------------------------------
// Edge index decode (int64 vs int32 robust) + CSR build
// ---------------------------------------------------------------------------
__global__ void detect_kernel(const void* ei) {
    if (threadIdx.x == 0 && blockIdx.x == 0) {
        const long long* p = (const long long*)ei;
        int ok = 1;
        for (int i = 0; i < 64; i++) {
            long long v = p[i];
            if (v < 0 || v >= NNODES) { ok = 0; break; }
        }
        g_is64 = ok;
    }
}

__global__ void decode_hist_kernel(const void* ei, int E) {
    int i = blockIdx.x * blockDim.x + threadIdx.x;
    if (i >= E) return;
    int s, d;
    if (g_is64) {
        const long long* p = (const long long*)ei;
        s = (int)p[i];
        d = (int)p[(size_t)E + i];
    } else {
        const int* p = (const int*)ei;
        s = p[i];
        d = p[E + i];
    }
    g_src[i] = s;
    g_dst[i] = d;
    atomicAdd(&g_deg[d], 1);
}

__global__ void scan_kernel(int n) {
    __shared__ int ssum[1024];
    const int tid = threadIdx.x;
    const int chunk = (n + 1023) >> 10;
    const int b = tid * chunk;
    const int e = min(b + chunk, n);
    int s = 0;
    for (int i = b; i < e; i++) s += g_deg[i];
    ssum[tid] = s;
    __syncthreads();
    for (int off = 1; off < 1024; off <<= 1) {
        int v = (tid >= off) ? ssum[tid - off] : 0;
        __syncthreads();
        ssum[tid] += v;
        __syncthreads();
    }
    int run = (tid > 0) ? ssum[tid - 1] : 0;
    for (int i = b; i < e; i++) { g_rowptr[i] = run; run += g_deg[i]; }
    if (tid == 0) g_rowptr[n] = ssum[1023];
}

__global__ void scatter_kernel(int E) {
    int i = blockIdx.x * blockDim.x + threadIdx.x;
    if (i >= E) return;
    int d = g_dst[i];
    int pos = g_rowptr[d] + atomicAdd(&g_cnt[d], 1);
    g_srcSorted[pos] = g_src[i];
}

// ---------------------------------------------------------------------------
// Fused triple GEMM, fp32 with packed f32x2 FMA.
//   C_i[nrows, 128] = A[nrows,128] @ B_i[128,128] + bias_i   (i = 0..2)
// 128 rows/CTA, 256 threads (8 warps x 16 rows), lane covers 4 cols (2 f32x2).
// smem: As 64KB + Bs 64KB = 128KB dynamic.
// ---------------------------------------------------------------------------
__global__ __launch_bounds__(256)
void gemm3_kernel(const float* __restrict__ A,
    const float* __restrict__ B0, const float* __restrict__ bias0, float* __restrict__ C0,
    const float* __restrict__ B1, const float* __restrict__ bias1, float* __restrict__ C1,
    const float* __restrict__ B2, const float* __restrict__ bias2, float* __restrict__ C2,
    int nrows)
{
    extern __shared__ float sm[];
    float* As = sm;                // 128 x 128
    float* Bs = sm + 128 * 128;    // 128 x 128
    const int tid = threadIdx.x, lane = tid & 31, warp = tid >> 5;
    const int row0 = blockIdx.x * 128;

    // load A tile (zero-padded tail)
    #pragma unroll
    for (int it = 0; it < 16; it++) {
        int idx4 = it * 256 + tid;         // 128 rows x 32 float4
        int r = idx4 >> 5, c4 = idx4 & 31;
        int gr = row0 + r;
        float4 v = make_float4(0.f, 0.f, 0.f, 0.f);
        if (gr < nrows) v = *(const float4*)(A + (size_t)gr * 128 + c4 * 4);
        *(float4*)(As + r * 128 + c4 * 4) = v;
    }

    const float* Bm[3]    = {B0, B1, B2};
    const float* biasm[3] = {bias0, bias1, bias2};
    float*       Cm[3]    = {C0, C1, C2};
    const int colb = lane * 4;
    const int rbase = warp * 16;

    #pragma unroll 1
    for (int mat = 0; mat < 3; mat++) {
        __syncthreads();   // As ready / prev compute done
        const float4* B4 = (const float4*)Bm[mat];
        #pragma unroll
        for (int it = 0; it < 16; it++) {
            int idx4 = it * 256 + tid;
            ((float4*)Bs)[idx4] = B4[idx4];
        }
        __syncthreads();

        uint64_t acc[16][2];
        #pragma unroll
        for (int r = 0; r < 16; r++) { acc[r][0] = 0ULL; acc[r][1] = 0ULL; }

        #pragma unroll 2
        for (int k = 0; k < 128; k += 2) {
            const float* bp = Bs + k * 128 + colb;
            uint64_t b00 = *(const uint64_t*)(bp);
            uint64_t b01 = *(const uint64_t*)(bp + 2);
            uint64_t b10 = *(const uint64_t*)(bp + 128);
            uint64_t b11 = *(const uint64_t*)(bp + 130);
            #pragma unroll
            for (int r = 0; r < 16; r++) {
                float2 a = *(const float2*)(As + (rbase + r) * 128 + k);
                uint64_t ax = pack2(a.x);
                uint64_t ay = pack2(a.y);
                fma2(acc[r][0], ax, b00); fma2(acc[r][1], ax, b01);
                fma2(acc[r][0], ay, b10); fma2(acc[r][1], ay, b11);
            }
        }

        float4 bs4 = *(const float4*)(biasm[mat] + colb);
        float* C = Cm[mat];
        #pragma unroll
        for (int r = 0; r < 16; r++) {
            int gr = row0 + rbase + r;
            if (gr < nrows) {
                float2 lo = unpack2(acc[r][0]);
                float2 hi = unpack2(acc[r][1]);
                float4 o = make_float4(lo.x + bs4.x, lo.y + bs4.y,
                                       hi.x + bs4.z, hi.y + bs4.w);
                *(float4*)(C + (size_t)gr * 128 + colb) = o;
            }
        }
    }
}

// Fused double GEMM, NCOLS=64 (layer 2). smem: As 64KB + Bs 32KB = 96KB
__global__ __launch_bounds__(256)
void gemm2_kernel(const float* __restrict__ A,
    const float* __restrict__ B0, const float* __restrict__ bias0, float* __restrict__ C0,
    const float* __restrict__ B1, const float* __restrict__ bias1, float* __restrict__ C1,
    int nrows)
{
    extern __shared__ float sm[];
    float* As = sm;                // 128 x 128
    float* Bs = sm + 128 * 128;    // 128 x 64
    const int tid = threadIdx.x, lane = tid & 31, warp = tid >> 5;
    const int row0 = blockIdx.x * 128;

    #pragma unroll
    for (int it = 0; it < 16; it++) {
        int idx4 = it * 256 + tid;
        int r = idx4 >> 5, c4 = idx4 & 31;
        int gr = row0 + r;
        float4 v = make_float4(0.f, 0.f, 0.f, 0.f);
        if (gr < nrows) v = *(const float4*)(A + (size_t)gr * 128 + c4 * 4);
        *(float4*)(As + r * 128 + c4 * 4) = v;
    }

    const float* Bm[2]    = {B0, B1};
    const float* biasm[2] = {bias0, bias1};
    float*       Cm[2]    = {C0, C1};
    const int colb = lane * 2;
    const int rbase = warp * 16;

    #pragma unroll 1
    for (int mat = 0; mat < 2; mat++) {
        __syncthreads();
        const float4* B4 = (const float4*)Bm[mat];
        #pragma unroll
        for (int it = 0; it < 8; it++) {
            int idx4 = it * 256 + tid;
            ((float4*)Bs)[idx4] = B4[idx4];
        }
        __syncthreads();

        uint64_t acc[16];
        #pragma unroll
        for (int r = 0; r < 16; r++) acc[r] = 0ULL;

        #pragma unroll 2
        for (int k = 0; k < 128; k += 2) {
            const float* bp = Bs + k * 64 + colb;
            uint64_t b0 = *(const uint64_t*)(bp);
            uint64_t b1 = *(const uint64_t*)(bp + 64);
            #pragma unroll
            for (int r = 0; r < 16; r++) {
                float2 a = *(const float2*)(As + (rbase + r) * 128 + k);
                fma2(acc[r], pack2(a.x), b0);
                fma2(acc[r], pack2(a.y), b1);
            }
        }

        float2 bs2 = *(const float2*)(biasm[mat] + colb);
        float* C = Cm[mat];
        #pragma unroll
        for (int r = 0; r < 16; r++) {
            int gr = row0 + rbase + r;
            if (gr < nrows) {
                float2 v = unpack2(acc[r]);
                float2 o = make_float2(v.x + bs2.x, v.y + bs2.y);
                *(float2*)(C + (size_t)gr * 64 + colb) = o;
            }
        }
    }
}

// ---------------------------------------------------------------------------
// Warp-per-node GATv2 aggregation, online softmax, 4-deep load pipeline.
// ---------------------------------------------------------------------------
template <int H, int C, bool RESELU>
__global__ void gat_aggregate_kernel(const float* __restrict__ xl,
                                     const float* __restrict__ xr,
                                     const float* __restrict__ att,
                                     const float* __restrict__ extra,
                                     float* __restrict__ out, int N)
{
    constexpr int HC = H * C;
    constexpr int R  = HC / 32;
    constexpr int L  = 32 / H;
    constexpr int PF = 4;
    const int n = (blockIdx.x * blockDim.x + threadIdx.x) >> 5;
    if (n >= N) return;
    const int lane = threadIdx.x & 31;
    const int fo = lane * R;

    float xrv[R], attv[R], acc[R];
    #pragma unroll
    for (int j = 0; j < R; j++) {
        xrv[j]  = xr[(size_t)n * HC + fo + j];
        attv[j] = att[fo + j];
        acc[j]  = 0.0f;
    }
    float m   = __int_as_float(0xff800000);
    float den = 0.0f;

    const int beg = g_rowptr[n];
    const int cnt = g_rowptr[n + 1] - beg;

    float buf[PF][R];
    // prologue: prefetch first PF edges
    #pragma unroll
    for (int j = 0; j < PF; j++) {
        if (j < cnt) {
            int s = g_srcSorted[beg + j];
            if (R == 4) {
                float4 t = *(const float4*)(xl + (size_t)s * HC + fo);
                buf[j][0] = t.x; buf[j][1] = t.y; buf[j][2] = t.z; buf[j][3] = t.w;
            } else {
                float2 t = *(const float2*)(xl + (size_t)s * HC + fo);
                buf[j][0] = t.x; buf[j][1] = t.y;
            }
        }
    }

    for (int base = 0; base < cnt; base += PF) {
        float cur[PF][R];
        #pragma unroll
        for (int j = 0; j < PF; j++)
            #pragma unroll
            for (int q = 0; q < R; q++) cur[j][q] = buf[j][q];

        // prefetch next group
        #pragma unroll
        for (int j = 0; j < PF; j++) {
            int nx = base + PF + j;
            if (nx < cnt) {
                int s = g_srcSorted[beg + nx];
                if (R == 4) {
                    float4 t = *(const float4*)(xl + (size_t)s * HC + fo);
                    buf[j][0] = t.x; buf[j][1] = t.y; buf[j][2] = t.z; buf[j][3] = t.w;
                } else {
                    float2 t = *(const float2*)(xl + (size_t)s * HC + fo);
                    buf[j][0] = t.x; buf[j][1] = t.y;
                }
            }
        }

        // process current group
        #pragma unroll
        for (int j = 0; j < PF; j++) {
            if (base + j < cnt) {
                float lg = 0.0f;
                #pragma unroll
                for (int q = 0; q < R; q++) {
                    float v = cur[j][q] + xrv[q];
                    v = v > 0.0f ? v : 0.2f * v;
                    lg += v * attv[q];
                }
                #pragma unroll
                for (int off = L >> 1; off; off >>= 1)
                    lg += __shfl_xor_sync(0xffffffffu, lg, off);

                float mn = fmaxf(m, lg);
                float sc = __expf(m - mn);
                float p  = __expf(lg - mn);
                den = den * sc + p;
                #pragma unroll
                for (int q = 0; q < R; q++) acc[q] = acc[q] * sc + p * cur[j][q];
                m = mn;
            }
        }
    }

    const float inv = 1.0f / (den + 1e-16f);
    #pragma unroll
    for (int j = 0; j < R; j++) {
        float v = acc[j] * inv;
        if (RESELU) {
            v += extra[(size_t)n * HC + fo + j];
            v = v > 0.0f ? v : (__expf(v) - 1.0f);
        } else {
            v += extra[fo + j];
        }
        out[(size_t)n * HC + fo + j] = v;
    }
}

// ---------------------------------------------------------------------------
// Launch
// ---------------------------------------------------------------------------
extern "C" void kernel_launch(void* const* d_in, const int* in_sizes, int n_in,
                              void* d_out, int out_size) {
    const float* x    = (const float*)d_in[0];
    const void*  ei   = d_in[1];
    const float* Wl0  = (const float*)d_in[2];
    const float* bl0  = (const float*)d_in[3];
    const float* Wr0  = (const float*)d_in[4];
    const float* br0  = (const float*)d_in[5];
    const float* att0 = (const float*)d_in[6];
    const float* b0   = (const float*)d_in[7];
    const float* res0 = (const float*)d_in[8];
    const float* Wl1  = (const float*)d_in[9];
    const float* bl1  = (const float*)d_in[10];
    const float* Wr1  = (const float*)d_in[11];
    const float* br1  = (const float*)d_in[12];
    const float* att1 = (const float*)d_in[13];
    const float* b1   = (const float*)d_in[14];
    const float* res1 = (const float*)d_in[15];
    const float* Wl2  = (const float*)d_in[16];
    const float* bl2  = (const float*)d_in[17];
    const float* Wr2  = (const float*)d_in[18];
    const float* br2  = (const float*)d_in[19];
    const float* att2 = (const float*)d_in[20];
    const float* b2   = (const float*)d_in[21];
    float* out = (float*)d_out;

    const int N = in_sizes[0] / 128;
    const int E = in_sizes[1] / 2;

    float *p_xl, *p_xr, *p_h, *p_acc;
    int *p_deg, *p_cnt;
    cudaGetSymbolAddress((void**)&p_xl,  g_xl);
    cudaGetSymbolAddress((void**)&p_xr,  g_xr);
    cudaGetSymbolAddress((void**)&p_h,   g_h);
    cudaGetSymbolAddress((void**)&p_acc, g_acc);
    cudaGetSymbolAddress((void**)&p_deg, g_deg);
    cudaGetSymbolAddress((void**)&p_cnt, g_cnt);

    const int sm3 = (128 * 128 + 128 * 128) * 4;  // 128KB
    const int sm2 = (128 * 128 + 128 * 64) * 4;   // 96KB
    static bool attr_done = false;
    if (!attr_done) {
        cudaFuncSetAttribute(gemm3_kernel, cudaFuncAttributeMaxDynamicSharedMemorySize, sm3);
        cudaFuncSetAttribute(gemm2_kernel, cudaFuncAttributeMaxDynamicSharedMemorySize, sm2);
        attr_done = true;
    }

    const int TB = 256;
    const int gemm_blocks = (N + 127) / 128;   // 391
    const int node_blocks = (N + 7) / 8;

    // ---- CSR build ----
    detect_kernel<<<1, 32>>>(ei);
    cudaMemsetAsync(p_deg, 0, (size_t)N * sizeof(int), 0);
    cudaMemsetAsync(p_cnt, 0, (size_t)N * sizeof(int), 0);
    decode_hist_kernel<<<(E + TB - 1) / TB, TB>>>(ei, E);
    scan_kernel<<<1, 1024>>>(N);
    scatter_kernel<<<(E + TB - 1) / TB, TB>>>(E);

    // ---- layer 0 ----
    gemm3_kernel<<<gemm_blocks, TB, sm3>>>(x, Wl0, bl0, p_xl, Wr0, br0, p_xr,
                                           res0, b0, p_acc, N);
    gat_aggregate_kernel<4, 32, true><<<node_blocks, TB>>>(p_xl, p_xr, att0,
                                                           p_acc, p_h, N);
    // ---- layer 1 ----
    gemm3_kernel<<<gemm_blocks, TB, sm3>>>(p_h, Wl1, bl1, p_xl, Wr1, br1, p_xr,
                                           res1, b1, p_acc, N);
    gat_aggregate_kernel<4, 32, true><<<node_blocks, TB>>>(p_xl, p_xr, att1,
                                                           p_acc, p_h, N);
    // ---- layer 2 ----
    gemm2_kernel<<<gemm_blocks, TB, sm2>>>(p_h, Wl2, bl2, p_xl, Wr2, br2, p_xr, N);
    gat_aggregate_kernel<1, 64, false><<<node_blocks, TB>>>(p_xl, p_xr, att2,
                                                            b2, out, N);
}

// round 7
// speedup vs baseline: 1.3017x; 1.1396x over previous
#include <cuda_runtime.h>
#include <math.h>
#include <stdint.h>

#define NNODES 50000
#define NEDGES 800000

// ---------------------------------------------------------------------------
// Scratch (__device__ globals; no cudaMalloc allowed).
// g_deg / g_cnt are zero at process start (static init) and re-zeroed by
// cleanup_kernel at the END of every kernel_launch, so every call starts
// from the same state (deterministic across correctness run + graph replays).
// ---------------------------------------------------------------------------
__device__ float g_xl[NNODES * 128];
__device__ float g_xr[NNODES * 128];
__device__ float g_h[NNODES * 128];      // layer input (post-ELU)
__device__ float g_acc[NNODES * 128];    // residual accumulator (A@res + b)
__device__ int   g_src[NEDGES];
__device__ int   g_dst[NEDGES];
__device__ int   g_srcSorted[NEDGES];    // src ids grouped by dst (CSR)
__device__ int   g_deg[NNODES];
__device__ int   g_cnt[NNODES];
__device__ int   g_rowptr[NNODES + 1];

// ---------------------------------------------------------------------------
// Packed f32x2 helpers (sm_100+ PTX)
// ---------------------------------------------------------------------------
__device__ __forceinline__ uint64_t pack2(float x) {
    uint64_t r;
    asm("mov.b64 %0, {%1, %1};" : "=l"(r) : "f"(x));
    return r;
}
__device__ __forceinline__ void fma2(uint64_t& d, uint64_t a, uint64_t b) {
    asm("fma.rn.f32x2 %0, %1, %2, %0;" : "+l"(d) : "l"(a), "l"(b));
}
__device__ __forceinline__ float2 unpack2(uint64_t v) {
    float2 r;
    asm("mov.b64 {%0, %1}, %2;" : "=f"(r.x), "=f"(r.y) : "l"(v));
    return r;
}

// ---------------------------------------------------------------------------
// CSR build. decode self-detects int64 vs int32 (every block computes the
// same answer from the first 16 int64 slots — no cross-kernel dependency).
// ---------------------------------------------------------------------------
__global__ void decode_hist_kernel(const void* ei, int E) {
    const long long* p64 = (const long long*)ei;
    bool is64 = true;
    #pragma unroll
    for (int j = 0; j < 16; j++) {
        long long v = p64[j];
        if (v < 0 || v >= NNODES) { is64 = false; }
    }
    int i = blockIdx.x * blockDim.x + threadIdx.x;
    if (i >= E) return;
    int s, d;
    if (is64) {
        s = (int)p64[i];
        d = (int)p64[(size_t)E + i];
    } else {
        const int* p = (const int*)ei;
        s = p[i];
        d = p[E + i];
    }
    g_src[i] = s;
    g_dst[i] = d;
    atomicAdd(&g_deg[d], 1);
}

// single-block exclusive scan over N degrees -> rowptr[0..N]
__global__ void scan_kernel(int n) {
    __shared__ int ssum[1024];
    const int tid = threadIdx.x;
    const int chunk = (n + 1023) >> 10;
    const int b = tid * chunk;
    const int e = min(b + chunk, n);
    int s = 0;
    for (int i = b; i < e; i++) s += g_deg[i];
    ssum[tid] = s;
    __syncthreads();
    for (int off = 1; off < 1024; off <<= 1) {
        int v = (tid >= off) ? ssum[tid - off] : 0;
        __syncthreads();
        ssum[tid] += v;
        __syncthreads();
    }
    int run = (tid > 0) ? ssum[tid - 1] : 0;
    for (int i = b; i < e; i++) { g_rowptr[i] = run; run += g_deg[i]; }
    if (tid == 0) g_rowptr[n] = ssum[1023];
}

__global__ void scatter_kernel(int E) {
    int i = blockIdx.x * blockDim.x + threadIdx.x;
    if (i >= E) return;
    int d = g_dst[i];
    int pos = g_rowptr[d] + atomicAdd(&g_cnt[d], 1);
    g_srcSorted[pos] = g_src[i];
}

__global__ void cleanup_kernel(int n) {
    int i = blockIdx.x * blockDim.x + threadIdx.x;
    if (i < n) { g_deg[i] = 0; g_cnt[i] = 0; }
}

// ---------------------------------------------------------------------------
// Fused triple GEMM, fp32 with packed f32x2 FMA.
//   C_i[nrows, 128] = A[nrows,128] @ B_i[128,128] + bias_i   (i = 0..2)
// 64 rows/CTA, 256 threads (8 warps x 8 rows), lane covers 4 cols (2 f32x2).
// smem: As 32KB + Bs 64KB = 96KB -> 2 CTAs/SM.
// ---------------------------------------------------------------------------
__global__ __launch_bounds__(256)
void gemm3_kernel(const float* __restrict__ A,
    const float* __restrict__ B0, const float* __restrict__ bias0, float* __restrict__ C0,
    const float* __restrict__ B1, const float* __restrict__ bias1, float* __restrict__ C1,
    const float* __restrict__ B2, const float* __restrict__ bias2, float* __restrict__ C2,
    int nrows)
{
    extern __shared__ float sm[];
    float* As = sm;               // 64 x 128
    float* Bs = sm + 64 * 128;    // 128 x 128
    const int tid = threadIdx.x, lane = tid & 31, warp = tid >> 5;
    const int row0 = blockIdx.x * 64;

    // load A tile (zero-padded tail)
    #pragma unroll
    for (int it = 0; it < 8; it++) {
        int idx4 = it * 256 + tid;         // 64 rows x 32 float4
        int r = idx4 >> 5, c4 = idx4 & 31;
        int gr = row0 + r;
        float4 v = make_float4(0.f, 0.f, 0.f, 0.f);
        if (gr < nrows) v = *(const float4*)(A + (size_t)gr * 128 + c4 * 4);
        *(float4*)(As + r * 128 + c4 * 4) = v;
    }

    const float* Bm[3]    = {B0, B1, B2};
    const float* biasm[3] = {bias0, bias1, bias2};
    float*       Cm[3]    = {C0, C1, C2};
    const int colb = lane * 4;
    const int rbase = warp * 8;

    #pragma unroll 1
    for (int mat = 0; mat < 3; mat++) {
        __syncthreads();   // As ready / prev compute done
        const float4* B4 = (const float4*)Bm[mat];
        #pragma unroll
        for (int it = 0; it < 16; it++) {
            int idx4 = it * 256 + tid;
            ((float4*)Bs)[idx4] = B4[idx4];
        }
        __syncthreads();

        uint64_t acc[8][2];
        #pragma unroll
        for (int r = 0; r < 8; r++) { acc[r][0] = 0ULL; acc[r][1] = 0ULL; }

        #pragma unroll 4
        for (int k = 0; k < 128; k += 2) {
            // B fragments: 4 cols x 2 k-steps = 4 u64
            float4 bA = *(const float4*)(Bs + k * 128 + colb);
            float4 bB = *(const float4*)(Bs + (k + 1) * 128 + colb);
            uint64_t b00 = ((const uint64_t*)&bA)[0];
            uint64_t b01 = ((const uint64_t*)&bA)[1];
            uint64_t b10 = ((const uint64_t*)&bB)[0];
            uint64_t b11 = ((const uint64_t*)&bB)[1];
            #pragma unroll
            for (int r = 0; r < 8; r++) {
                float2 a = *(const float2*)(As + (rbase + r) * 128 + k);
                uint64_t ax = pack2(a.x);
                uint64_t ay = pack2(a.y);
                fma2(acc[r][0], ax, b00); fma2(acc[r][1], ax, b01);
                fma2(acc[r][0], ay, b10); fma2(acc[r][1], ay, b11);
            }
        }

        float4 bs4 = *(const float4*)(biasm[mat] + colb);
        float* C = Cm[mat];
        #pragma unroll
        for (int r = 0; r < 8; r++) {
            int gr = row0 + rbase + r;
            if (gr < nrows) {
                float2 lo = unpack2(acc[r][0]);
                float2 hi = unpack2(acc[r][1]);
                float4 o = make_float4(lo.x + bs4.x, lo.y + bs4.y,
                                       hi.x + bs4.z, hi.y + bs4.w);
                *(float4*)(C + (size_t)gr * 128 + colb) = o;
            }
        }
    }
}

// Fused double GEMM, NCOLS=64 (layer 2). smem: As 32KB + Bs 32KB = 64KB
__global__ __launch_bounds__(256)
void gemm2_kernel(const float* __restrict__ A,
    const float* __restrict__ B0, const float* __restrict__ bias0, float* __restrict__ C0,
    const float* __restrict__ B1, const float* __restrict__ bias1, float* __restrict__ C1,
    int nrows)
{
    extern __shared__ float sm[];
    float* As = sm;               // 64 x 128
    float* Bs = sm + 64 * 128;    // 128 x 64
    const int tid = threadIdx.x, lane = tid & 31, warp = tid >> 5;
    const int row0 = blockIdx.x * 64;

    #pragma unroll
    for (int it = 0; it < 8; it++) {
        int idx4 = it * 256 + tid;
        int r = idx4 >> 5, c4 = idx4 & 31;
        int gr = row0 + r;
        float4 v = make_float4(0.f, 0.f, 0.f, 0.f);
        if (gr < nrows) v = *(const float4*)(A + (size_t)gr * 128 + c4 * 4);
        *(float4*)(As + r * 128 + c4 * 4) = v;
    }

    const float* Bm[2]    = {B0, B1};
    const float* biasm[2] = {bias0, bias1};
    float*       Cm[2]    = {C0, C1};
    const int colb = lane * 2;
    const int rbase = warp * 8;

    #pragma unroll 1
    for (int mat = 0; mat < 2; mat++) {
        __syncthreads();
        const float4* B4 = (const float4*)Bm[mat];
        #pragma unroll
        for (int it = 0; it < 8; it++) {
            int idx4 = it * 256 + tid;
            ((float4*)Bs)[idx4] = B4[idx4];
        }
        __syncthreads();

        uint64_t acc[8];
        #pragma unroll
        for (int r = 0; r < 8; r++) acc[r] = 0ULL;

        #pragma unroll 4
        for (int k = 0; k < 128; k += 2) {
            uint64_t b0 = *(const uint64_t*)(Bs + k * 64 + colb);
            uint64_t b1 = *(const uint64_t*)(Bs + (k + 1) * 64 + colb);
            #pragma unroll
            for (int r = 0; r < 8; r++) {
                float2 a = *(const float2*)(As + (rbase + r) * 128 + k);
                fma2(acc[r], pack2(a.x), b0);
                fma2(acc[r], pack2(a.y), b1);
            }
        }

        float2 bs2 = *(const float2*)(biasm[mat] + colb);
        float* C = Cm[mat];
        #pragma unroll
        for (int r = 0; r < 8; r++) {
            int gr = row0 + rbase + r;
            if (gr < nrows) {
                float2 v = unpack2(acc[r]);
                float2 o = make_float2(v.x + bs2.x, v.y + bs2.y);
                *(float2*)(C + (size_t)gr * 64 + colb) = o;
            }
        }
    }
}

// ---------------------------------------------------------------------------
// Warp-per-node GATv2 aggregation with online softmax (R3 body).
// ---------------------------------------------------------------------------
template <int H, int C, bool RESELU>
__global__ void gat_aggregate_kernel(const float* __restrict__ xl,
                                     const float* __restrict__ xr,
                                     const float* __restrict__ att,
                                     const float* __restrict__ extra,
                                     float* __restrict__ out, int N)
{
    constexpr int HC = H * C;
    constexpr int R  = HC / 32;
    constexpr int L  = 32 / H;
    const int n = (blockIdx.x * blockDim.x + threadIdx.x) >> 5;
    if (n >= N) return;
    const int lane = threadIdx.x & 31;
    const int fo = lane * R;

    float xrv[R], attv[R], acc[R];
    #pragma unroll
    for (int j = 0; j < R; j++) {
        xrv[j]  = xr[(size_t)n * HC + fo + j];
        attv[j] = att[fo + j];
        acc[j]  = 0.0f;
    }
    float m   = __int_as_float(0xff800000);
    float den = 0.0f;

    const int beg = g_rowptr[n], end = g_rowptr[n + 1];
    for (int i = beg; i < end; i++) {
        const int s = g_srcSorted[i];
        float a[R];
        if (R == 4) {
            float4 t = *(const float4*)(xl + (size_t)s * HC + fo);
            a[0] = t.x; a[1] = t.y; a[2] = t.z; a[3] = t.w;
        } else {
            float2 t = *(const float2*)(xl + (size_t)s * HC + fo);
            a[0] = t.x; a[1] = t.y;
        }
        float lg = 0.0f;
        #pragma unroll
        for (int j = 0; j < R; j++) {
            float v = a[j] + xrv[j];
            v = v > 0.0f ? v : 0.2f * v;
            lg += v * attv[j];
        }
        #pragma unroll
        for (int off = L >> 1; off; off >>= 1)
            lg += __shfl_xor_sync(0xffffffffu, lg, off);

        float mn = fmaxf(m, lg);
        float sc = __expf(m - mn);
        float p  = __expf(lg - mn);
        den = den * sc + p;
        #pragma unroll
        for (int j = 0; j < R; j++) acc[j] = acc[j] * sc + p * a[j];
        m = mn;
    }

    const float inv = 1.0f / (den + 1e-16f);
    #pragma unroll
    for (int j = 0; j < R; j++) {
        float v = acc[j] * inv;
        if (RESELU) {
            v += extra[(size_t)n * HC + fo + j];
            v = v > 0.0f ? v : (__expf(v) - 1.0f);
        } else {
            v += extra[fo + j];
        }
        out[(size_t)n * HC + fo + j] = v;
    }
}

// ---------------------------------------------------------------------------
// Launch. Kernel order matters for profiling: the 4th kernel launch is the
// one ncu captures -> put gemm3 (layer 0) there.
// ---------------------------------------------------------------------------
extern "C" void kernel_launch(void* const* d_in, const int* in_sizes, int n_in,
                              void* d_out, int out_size) {
    const float* x    = (const float*)d_in[0];
    const void*  ei   = d_in[1];
    const float* Wl0  = (const float*)d_in[2];
    const float* bl0  = (const float*)d_in[3];
    const float* Wr0  = (const float*)d_in[4];
    const float* br0  = (const float*)d_in[5];
    const float* att0 = (const float*)d_in[6];
    const float* b0   = (const float*)d_in[7];
    const float* res0 = (const float*)d_in[8];
    const float* Wl1  = (const float*)d_in[9];
    const float* bl1  = (const float*)d_in[10];
    const float* Wr1  = (const float*)d_in[11];
    const float* br1  = (const float*)d_in[12];
    const float* att1 = (const float*)d_in[13];
    const float* b1   = (const float*)d_in[14];
    const float* res1 = (const float*)d_in[15];
    const float* Wl2  = (const float*)d_in[16];
    const float* bl2  = (const float*)d_in[17];
    const float* Wr2  = (const float*)d_in[18];
    const float* br2  = (const float*)d_in[19];
    const float* att2 = (const float*)d_in[20];
    const float* b2   = (const float*)d_in[21];
    float* out = (float*)d_out;

    const int N = in_sizes[0] / 128;
    const int E = in_sizes[1] / 2;

    float *p_xl, *p_xr, *p_h, *p_acc;
    cudaGetSymbolAddress((void**)&p_xl,  g_xl);
    cudaGetSymbolAddress((void**)&p_xr,  g_xr);
    cudaGetSymbolAddress((void**)&p_h,   g_h);
    cudaGetSymbolAddress((void**)&p_acc, g_acc);

    const int sm3 = (64 * 128 + 128 * 128) * 4;   // 96KB
    const int sm2 = (64 * 128 + 128 * 64) * 4;    // 64KB
    static bool attr_done = false;
    if (!attr_done) {
        cudaFuncSetAttribute(gemm3_kernel, cudaFuncAttributeMaxDynamicSharedMemorySize, sm3);
        cudaFuncSetAttribute(gemm2_kernel, cudaFuncAttributeMaxDynamicSharedMemorySize, sm2);
        attr_done = true;
    }

    const int TB = 256;
    const int gemm_blocks = (N + 63) / 64;      // 782
    const int node_blocks = (N + 7) / 8;

    // ---- CSR build (g_deg/g_cnt are zero on entry; cleanup re-zeroes at end)
    decode_hist_kernel<<<(E + TB - 1) / TB, TB>>>(ei, E);    // launch 1
    scan_kernel<<<1, 1024>>>(N);                             // launch 2
    scatter_kernel<<<(E + TB - 1) / TB, TB>>>(E);            // launch 3

    // ---- layer 0 ----
    gemm3_kernel<<<gemm_blocks, TB, sm3>>>(x, Wl0, bl0, p_xl, Wr0, br0, p_xr,
                                           res0, b0, p_acc, N);   // launch 4 (profiled)
    gat_aggregate_kernel<4, 32, true><<<node_blocks, TB>>>(p_xl, p_xr, att0,
                                                           p_acc, p_h, N);
    // ---- layer 1 ----
    gemm3_kernel<<<gemm_blocks, TB, sm3>>>(p_h, Wl1, bl1, p_xl, Wr1, br1, p_xr,
                                           res1, b1, p_acc, N);
    gat_aggregate_kernel<4, 32, true><<<node_blocks, TB>>>(p_xl, p_xr, att1,
                                                           p_acc, p_h, N);
    // ---- layer 2 ----
    gemm2_kernel<<<gemm_blocks, TB, sm2>>>(p_h, Wl2, bl2, p_xl, Wr2, br2, p_xr, N);
    gat_aggregate_kernel<1, 64, false><<<node_blocks, TB>>>(p_xl, p_xr, att2,
                                                            b2, out, N);

    // ---- reset deg/cnt for the next invocation ----
    cleanup_kernel<<<(N + TB - 1) / TB, TB>>>(N);
}